// round 1
// baseline (speedup 1.0000x reference)
#include <cuda_runtime.h>
#include <cuda_bf16.h>

// Problem constants
#define S_TOK   4096            // B*T tokens
#define NSLOT   8192            // S*K slots
#define DM      768
#define DF      3072
#define NE      8

#define BM 128
#define BN 128
#define BK 16

// ---- scratch (device globals; no allocation allowed) ----
__device__ int   g_count[NE];
__device__ int   g_list[NE][NSLOT];
__device__ float g_w[2][S_TOK];
__device__ float g_h[(size_t)NSLOT * DF];    // ~100.7 MB expert-hidden
__device__ float g_so[(size_t)NSLOT * DM];   // ~25.2 MB per-slot FFN output

// ---------------------------------------------------------------------------
// 0. reset routing counters (must happen every replay)
// ---------------------------------------------------------------------------
__global__ void zero_counts_kernel() {
    if (threadIdx.x < NE) g_count[threadIdx.x] = 0;
}

// ---------------------------------------------------------------------------
// 1. gate: warp per token. logits = x @ Wg, top-2, renormalized softmax
//    weights, append slots to per-expert lists.
// ---------------------------------------------------------------------------
__global__ void __launch_bounds__(256) gate_kernel(const float* __restrict__ x,
                                                   const float* __restrict__ Wg) {
    int warp = threadIdx.x >> 5;
    int lane = threadIdx.x & 31;
    int s = blockIdx.x * 8 + warp;
    if (s >= S_TOK) return;

    const float* xr = x + (size_t)s * DM;
    float acc[NE];
#pragma unroll
    for (int e = 0; e < NE; e++) acc[e] = 0.f;

    for (int m = lane; m < DM; m += 32) {
        float xv = xr[m];
        const float* wr = Wg + m * NE;
#pragma unroll
        for (int e = 0; e < NE; e++) acc[e] += xv * wr[e];
    }
#pragma unroll
    for (int e = 0; e < NE; e++) {
#pragma unroll
        for (int o = 16; o > 0; o >>= 1)
            acc[e] += __shfl_xor_sync(0xffffffffu, acc[e], o);
    }

    if (lane == 0) {
        // top-1 (strict > keeps lowest index on ties, matching jax top_k)
        int a = 0;
#pragma unroll
        for (int e = 1; e < NE; e++) if (acc[e] > acc[a]) a = e;
        // top-2 excluding a
        int b = (a == 0) ? 1 : 0;
#pragma unroll
        for (int e = 0; e < NE; e++)
            if (e != a && acc[e] > acc[b]) b = e;

        // renormalized top-2 softmax weight: exp(la)/(exp(la)+exp(lb))
        float eb = __expf(acc[b] - acc[a]);   // <= 1
        float inv = 1.f / (1.f + eb);
        g_w[0][s] = inv;
        g_w[1][s] = eb * inv;

        int pa = atomicAdd(&g_count[a], 1);
        g_list[a][pa] = s;              // slot for k=0
        int pb = atomicAdd(&g_count[b], 1);
        g_list[b][pb] = S_TOK + s;      // slot for k=1
    }
}

// ---------------------------------------------------------------------------
// 2. grouped GEMM 1: h[slot, :] = relu( x[tok] @ W1[e] + b1[e] )
//    grid: (DF/BN, NSLOT/BM, NE). Tiles beyond this expert's count early-exit.
// ---------------------------------------------------------------------------
__global__ void __launch_bounds__(256) gemm1_kernel(const float* __restrict__ x,
                                                    const float* __restrict__ W1,
                                                    const float* __restrict__ b1) {
    int e = blockIdx.z;
    int cnt = g_count[e];
    int row0 = blockIdx.y * BM;
    if (row0 >= cnt) return;
    int f0 = blockIdx.x * BN;

    __shared__ float As[BK][BM + 4];
    __shared__ float Bs[BK][BN];
    __shared__ int   rows[BM];

    int tid = threadIdx.x;
    if (tid < BM) {
        int r = row0 + tid;
        rows[tid] = (r < cnt) ? g_list[e][r] : -1;
    }
    __syncthreads();

    const float* Wb = W1 + (size_t)e * DM * DF;
    int tx = tid & 15, ty = tid >> 4;

    float acc[8][8];
#pragma unroll
    for (int i = 0; i < 8; i++)
#pragma unroll
        for (int j = 0; j < 8; j++) acc[i][j] = 0.f;

    for (int kt = 0; kt < DM; kt += BK) {
        // A gather: 128 rows x 16 cols = 512 float4
#pragma unroll
        for (int l = 0; l < 2; l++) {
            int idx = tid + l * 256;
            int r = idx >> 2;
            int kq = idx & 3;
            int slot = rows[r];
            float4 v = make_float4(0.f, 0.f, 0.f, 0.f);
            if (slot >= 0) {
                int tok = slot & (S_TOK - 1);
                v = *(const float4*)(x + (size_t)tok * DM + kt + kq * 4);
            }
            As[kq * 4 + 0][r] = v.x;
            As[kq * 4 + 1][r] = v.y;
            As[kq * 4 + 2][r] = v.z;
            As[kq * 4 + 3][r] = v.w;
        }
        // B: 16 rows x 128 cols
#pragma unroll
        for (int l = 0; l < 2; l++) {
            int idx = tid + l * 256;
            int kr = idx >> 5;
            int cq = idx & 31;
            float4 v = *(const float4*)(Wb + (size_t)(kt + kr) * DF + f0 + cq * 4);
            *(float4*)&Bs[kr][cq * 4] = v;
        }
        __syncthreads();

#pragma unroll
        for (int kk = 0; kk < BK; kk++) {
            float a[8], b[8];
            *(float4*)(a)     = *(const float4*)&As[kk][ty * 8];
            *(float4*)(a + 4) = *(const float4*)&As[kk][ty * 8 + 4];
            *(float4*)(b)     = *(const float4*)&Bs[kk][tx * 8];
            *(float4*)(b + 4) = *(const float4*)&Bs[kk][tx * 8 + 4];
#pragma unroll
            for (int i = 0; i < 8; i++)
#pragma unroll
                for (int j = 0; j < 8; j++) acc[i][j] += a[i] * b[j];
        }
        __syncthreads();
    }

    float4 bv0 = *(const float4*)(b1 + (size_t)e * DF + f0 + tx * 8);
    float4 bv1 = *(const float4*)(b1 + (size_t)e * DF + f0 + tx * 8 + 4);
#pragma unroll
    for (int i = 0; i < 8; i++) {
        int rr = ty * 8 + i;
        if (row0 + rr < cnt) {
            int slot = rows[rr];
            float* hp = g_h + (size_t)slot * DF + f0 + tx * 8;
            float4 r0, r1;
            r0.x = fmaxf(acc[i][0] + bv0.x, 0.f);
            r0.y = fmaxf(acc[i][1] + bv0.y, 0.f);
            r0.z = fmaxf(acc[i][2] + bv0.z, 0.f);
            r0.w = fmaxf(acc[i][3] + bv0.w, 0.f);
            r1.x = fmaxf(acc[i][4] + bv1.x, 0.f);
            r1.y = fmaxf(acc[i][5] + bv1.y, 0.f);
            r1.z = fmaxf(acc[i][6] + bv1.z, 0.f);
            r1.w = fmaxf(acc[i][7] + bv1.w, 0.f);
            *(float4*)(hp)     = r0;
            *(float4*)(hp + 4) = r1;
        }
    }
}

// ---------------------------------------------------------------------------
// 3. grouped GEMM 2: so[slot, :] = h[slot] @ W2[e] + b2[e]
//    grid: (DM/BN, NSLOT/BM, NE)
// ---------------------------------------------------------------------------
__global__ void __launch_bounds__(256) gemm2_kernel(const float* __restrict__ W2,
                                                    const float* __restrict__ b2) {
    int e = blockIdx.z;
    int cnt = g_count[e];
    int row0 = blockIdx.y * BM;
    if (row0 >= cnt) return;
    int f0 = blockIdx.x * BN;

    __shared__ float As[BK][BM + 4];
    __shared__ float Bs[BK][BN];
    __shared__ int   rows[BM];

    int tid = threadIdx.x;
    if (tid < BM) {
        int r = row0 + tid;
        rows[tid] = (r < cnt) ? g_list[e][r] : -1;
    }
    __syncthreads();

    const float* Wb = W2 + (size_t)e * DF * DM;
    int tx = tid & 15, ty = tid >> 4;

    float acc[8][8];
#pragma unroll
    for (int i = 0; i < 8; i++)
#pragma unroll
        for (int j = 0; j < 8; j++) acc[i][j] = 0.f;

    for (int kt = 0; kt < DF; kt += BK) {
#pragma unroll
        for (int l = 0; l < 2; l++) {
            int idx = tid + l * 256;
            int r = idx >> 2;
            int kq = idx & 3;
            int slot = rows[r];
            float4 v = make_float4(0.f, 0.f, 0.f, 0.f);
            if (slot >= 0) {
                v = *(const float4*)(g_h + (size_t)slot * DF + kt + kq * 4);
            }
            As[kq * 4 + 0][r] = v.x;
            As[kq * 4 + 1][r] = v.y;
            As[kq * 4 + 2][r] = v.z;
            As[kq * 4 + 3][r] = v.w;
        }
#pragma unroll
        for (int l = 0; l < 2; l++) {
            int idx = tid + l * 256;
            int kr = idx >> 5;
            int cq = idx & 31;
            float4 v = *(const float4*)(Wb + (size_t)(kt + kr) * DM + f0 + cq * 4);
            *(float4*)&Bs[kr][cq * 4] = v;
        }
        __syncthreads();

#pragma unroll
        for (int kk = 0; kk < BK; kk++) {
            float a[8], b[8];
            *(float4*)(a)     = *(const float4*)&As[kk][ty * 8];
            *(float4*)(a + 4) = *(const float4*)&As[kk][ty * 8 + 4];
            *(float4*)(b)     = *(const float4*)&Bs[kk][tx * 8];
            *(float4*)(b + 4) = *(const float4*)&Bs[kk][tx * 8 + 4];
#pragma unroll
            for (int i = 0; i < 8; i++)
#pragma unroll
                for (int j = 0; j < 8; j++) acc[i][j] += a[i] * b[j];
        }
        __syncthreads();
    }

    float4 bv0 = *(const float4*)(b2 + (size_t)e * DM + f0 + tx * 8);
    float4 bv1 = *(const float4*)(b2 + (size_t)e * DM + f0 + tx * 8 + 4);
#pragma unroll
    for (int i = 0; i < 8; i++) {
        int rr = ty * 8 + i;
        if (row0 + rr < cnt) {
            int slot = rows[rr];
            float* op = g_so + (size_t)slot * DM + f0 + tx * 8;
            float4 r0, r1;
            r0.x = acc[i][0] + bv0.x;
            r0.y = acc[i][1] + bv0.y;
            r0.z = acc[i][2] + bv0.z;
            r0.w = acc[i][3] + bv0.w;
            r1.x = acc[i][4] + bv1.x;
            r1.y = acc[i][5] + bv1.y;
            r1.z = acc[i][6] + bv1.z;
            r1.w = acc[i][7] + bv1.w;
            *(float4*)(op)     = r0;
            *(float4*)(op + 4) = r1;
        }
    }
}

// ---------------------------------------------------------------------------
// 4. combine: out[s,:] = w0[s]*so[s,:] + w1[s]*so[S+s,:]
// ---------------------------------------------------------------------------
__global__ void __launch_bounds__(256) combine_kernel(float* __restrict__ out) {
    int i4 = blockIdx.x * blockDim.x + threadIdx.x;   // float4 index
    const int N4 = S_TOK * DM / 4;
    if (i4 >= N4) return;
    int base = i4 * 4;
    int s = base / DM;
    float w0 = g_w[0][s];
    float w1 = g_w[1][s];
    float4 a = *(const float4*)(g_so + base);
    float4 b = *(const float4*)(g_so + (size_t)S_TOK * DM + base);
    float4 r;
    r.x = w0 * a.x + w1 * b.x;
    r.y = w0 * a.y + w1 * b.y;
    r.z = w0 * a.z + w1 * b.z;
    r.w = w0 * a.w + w1 * b.w;
    *(float4*)(out + base) = r;
}

// ---------------------------------------------------------------------------
extern "C" void kernel_launch(void* const* d_in, const int* in_sizes, int n_in,
                              void* d_out, int out_size) {
    const float* x  = (const float*)d_in[0];
    const float* Wg = (const float*)d_in[1];
    const float* W1 = (const float*)d_in[2];
    const float* b1 = (const float*)d_in[3];
    const float* W2 = (const float*)d_in[4];
    const float* b2 = (const float*)d_in[5];
    float* out = (float*)d_out;

    zero_counts_kernel<<<1, 32>>>();
    gate_kernel<<<S_TOK / 8, 256>>>(x, Wg);
    gemm1_kernel<<<dim3(DF / BN, NSLOT / BM, NE), 256>>>(x, W1, b1);
    gemm2_kernel<<<dim3(DM / BN, NSLOT / BM, NE), 256>>>(W2, b2);
    {
        const int N4 = S_TOK * DM / 4;
        combine_kernel<<<(N4 + 255) / 256, 256>>>(out);
    }
}

// round 3
// speedup vs baseline: 3.9236x; 3.9236x over previous
#include <cuda_runtime.h>
#include <cuda_fp16.h>

// Problem constants
#define S_TOK   4096
#define NSLOT   8192
#define DM      768
#define DF      3072
#define NE      8

#define BM 128
#define BN 128
#define BK 32
#define AS_STRIDE 56    // halves: 112B row stride, 16B-aligned, conflict-free ldmatrix
#define BS_STRIDE 136   // halves: 272B row stride, 16B-aligned, conflict-free ldmatrix

// ---- scratch (device globals; no allocation allowed) ----
__device__ int    g_count[NE];
__device__ int    g_list[NE][NSLOT];
__device__ float  g_w[2][S_TOK];
__device__ __half g_xh[(size_t)S_TOK * DM];
__device__ __half g_w1h[(size_t)NE * DM * DF];
__device__ __half g_w2h[(size_t)NE * DF * DM];
__device__ __half g_h[(size_t)NSLOT * DF];
__device__ float  g_so[(size_t)NSLOT * DM];

// ---------------------------------------------------------------------------
__global__ void zero_counts_kernel() {
    if (threadIdx.x < NE) g_count[threadIdx.x] = 0;
}

// ---------------------------------------------------------------------------
// float -> half converters (device-global destinations; DST tag selects)
// ---------------------------------------------------------------------------
template<int DST>
__global__ void __launch_bounds__(256) f2h_kernel(const float* __restrict__ src, int n4) {
    int i = blockIdx.x * blockDim.x + threadIdx.x;
    if (i >= n4) return;
    float4 v = ((const float4*)src)[i];
    __half2 a = __floats2half2_rn(v.x, v.y);
    __half2 b = __floats2half2_rn(v.z, v.w);
    uint2 pk;
    pk.x = *(unsigned int*)&a;
    pk.y = *(unsigned int*)&b;
    __half* dst = (DST == 0) ? g_xh : ((DST == 1) ? g_w1h : g_w2h);
    ((uint2*)dst)[i] = pk;
}

// ---------------------------------------------------------------------------
// gate: warp per token
// ---------------------------------------------------------------------------
__global__ void __launch_bounds__(256) gate_kernel(const float* __restrict__ x,
                                                   const float* __restrict__ Wg) {
    int warp = threadIdx.x >> 5;
    int lane = threadIdx.x & 31;
    int s = blockIdx.x * 8 + warp;
    if (s >= S_TOK) return;

    const float* xr = x + (size_t)s * DM;
    float acc[NE];
#pragma unroll
    for (int e = 0; e < NE; e++) acc[e] = 0.f;

    for (int m = lane; m < DM; m += 32) {
        float xv = xr[m];
        const float* wr = Wg + m * NE;
#pragma unroll
        for (int e = 0; e < NE; e++) acc[e] += xv * wr[e];
    }
#pragma unroll
    for (int e = 0; e < NE; e++) {
#pragma unroll
        for (int o = 16; o > 0; o >>= 1) {
            acc[e] += __shfl_xor_sync(0xffffffffu, acc[e], o);
        }
    }

    if (lane == 0) {
        int a = 0;
#pragma unroll
        for (int e = 1; e < NE; e++) {
            if (acc[e] > acc[a]) a = e;
        }
        int b = (a == 0) ? 1 : 0;
#pragma unroll
        for (int e = 0; e < NE; e++) {
            if (e != a && acc[e] > acc[b]) b = e;
        }

        float eb = __expf(acc[b] - acc[a]);
        float inv = 1.f / (1.f + eb);
        g_w[0][s] = inv;
        g_w[1][s] = eb * inv;

        int pa = atomicAdd(&g_count[a], 1);
        g_list[a][pa] = s;
        int pb = atomicAdd(&g_count[b], 1);
        g_list[b][pb] = S_TOK + s;
    }
}

// ---------------------------------------------------------------------------
// tensor-core helpers
// ---------------------------------------------------------------------------
__device__ __forceinline__ void ldsm_x4(unsigned& r0, unsigned& r1,
                                        unsigned& r2, unsigned& r3,
                                        const void* p) {
    unsigned a = (unsigned)__cvta_generic_to_shared(p);
    asm volatile("ldmatrix.sync.aligned.m8n8.x4.shared.b16 {%0,%1,%2,%3}, [%4];\n"
                 : "=r"(r0), "=r"(r1), "=r"(r2), "=r"(r3) : "r"(a));
}

__device__ __forceinline__ void ldsm_x4_t(unsigned& r0, unsigned& r1,
                                          unsigned& r2, unsigned& r3,
                                          const void* p) {
    unsigned a = (unsigned)__cvta_generic_to_shared(p);
    asm volatile("ldmatrix.sync.aligned.m8n8.x4.trans.shared.b16 {%0,%1,%2,%3}, [%4];\n"
                 : "=r"(r0), "=r"(r1), "=r"(r2), "=r"(r3) : "r"(a));
}

__device__ __forceinline__ void mma16816(float* c, const unsigned* a, const unsigned* b) {
    asm volatile(
        "mma.sync.aligned.m16n8k16.row.col.f32.f16.f16.f32 "
        "{%0,%1,%2,%3}, {%4,%5,%6,%7}, {%8,%9}, {%0,%1,%2,%3};\n"
        : "+f"(c[0]), "+f"(c[1]), "+f"(c[2]), "+f"(c[3])
        : "r"(a[0]), "r"(a[1]), "r"(a[2]), "r"(a[3]), "r"(b[0]), "r"(b[1]));
}

// ---------------------------------------------------------------------------
// Grouped GEMM (single body for both FFN layers).
//   GEMM1: A = g_xh[slot & (S-1)], W = g_w1h, bias+relu -> g_h (half)
//   GEMM2: A = g_h[slot],          W = g_w2h, bias      -> g_so (float)
// grid (NDIM/BN, NSLOT/BM, NE), 256 threads (8 warps, 64x32 warp tiles)
// ---------------------------------------------------------------------------
template<int KDIM, int NDIM, bool GEMM1>
__global__ void __launch_bounds__(256) moe_gemm(const float* __restrict__ bias) {
    const int e = blockIdx.z;
    const int cnt = g_count[e];
    const int row0 = blockIdx.y * BM;
    if (row0 >= cnt) return;
    const int f0 = blockIdx.x * BN;

    __shared__ __half As[BM][AS_STRIDE];
    __shared__ __half Bs[BK][BS_STRIDE];
    __shared__ int rows_s[BM];

    const int tid = threadIdx.x;
    const int lane = tid & 31;
    const int wid = tid >> 5;
    const int wm = (wid >> 2) * 64;
    const int wn = (wid & 3) * 32;

    if (tid < BM) {
        int r = row0 + tid;
        rows_s[tid] = (r < cnt) ? g_list[e][r] : -1;
    }
    __syncthreads();

    const __half* Ab = GEMM1 ? g_xh : g_h;
    const __half* Wb = (GEMM1 ? g_w1h : g_w2h) + (size_t)e * KDIM * NDIM;

    float c[4][4][4];
#pragma unroll
    for (int mi = 0; mi < 4; mi++) {
#pragma unroll
        for (int ni = 0; ni < 4; ni++) {
#pragma unroll
            for (int q = 0; q < 4; q++) {
                c[mi][ni][q] = 0.f;
            }
        }
    }

    for (int kt = 0; kt < KDIM; kt += BK) {
        // A tile: 128 rows x 32 halves = 512 uint4; 2 per thread (gathered)
#pragma unroll
        for (int l = 0; l < 2; l++) {
            int u = tid + l * 256;
            int r = u >> 2;
            int kq = u & 3;
            int slot = rows_s[r];
            uint4 v = make_uint4(0u, 0u, 0u, 0u);
            if (slot >= 0) {
                int arow = GEMM1 ? (slot & (S_TOK - 1)) : slot;
                v = *(const uint4*)(Ab + (size_t)arow * KDIM + kt + kq * 8);
            }
            *(uint4*)&As[r][kq * 8] = v;
        }
        // B tile: 32 k-rows x 128 n-cols = 512 uint4; 2 per thread
#pragma unroll
        for (int l = 0; l < 2; l++) {
            int u = tid + l * 256;
            int kr = u >> 4;
            int cq = u & 15;
            uint4 v = *(const uint4*)(Wb + (size_t)(kt + kr) * NDIM + f0 + cq * 8);
            *(uint4*)&Bs[kr][cq * 8] = v;
        }
        __syncthreads();

#pragma unroll
        for (int kc = 0; kc < BK; kc += 16) {
            unsigned af[4][4];
            unsigned bf[4][2];
#pragma unroll
            for (int mi = 0; mi < 4; mi++) {
                ldsm_x4(af[mi][0], af[mi][1], af[mi][2], af[mi][3],
                        &As[wm + mi * 16 + (lane & 15)][kc + (lane >> 4) * 8]);
            }
#pragma unroll
            for (int nj = 0; nj < 2; nj++) {
                ldsm_x4_t(bf[2 * nj][0], bf[2 * nj][1],
                          bf[2 * nj + 1][0], bf[2 * nj + 1][1],
                          &Bs[kc + (lane & 15)][wn + nj * 16 + (lane >> 4) * 8]);
            }
#pragma unroll
            for (int mi = 0; mi < 4; mi++) {
#pragma unroll
                for (int ni = 0; ni < 4; ni++) {
                    mma16816(c[mi][ni], af[mi], bf[ni]);
                }
            }
        }
        __syncthreads();
    }

    // epilogue
    const float* be = bias + (size_t)e * NDIM + f0;
    float bias0[4];
    float bias1[4];
#pragma unroll
    for (int ni = 0; ni < 4; ni++) {
        int col = wn + ni * 8 + (lane & 3) * 2;
        bias0[ni] = be[col];
        bias1[ni] = be[col + 1];
    }
#pragma unroll
    for (int mi = 0; mi < 4; mi++) {
#pragma unroll
        for (int hr = 0; hr < 2; hr++) {
            int rr = wm + mi * 16 + hr * 8 + (lane >> 2);
            int slot = rows_s[rr];
            if (slot >= 0) {
#pragma unroll
                for (int ni = 0; ni < 4; ni++) {
                    int col = wn + ni * 8 + (lane & 3) * 2;
                    float v0 = c[mi][ni][hr * 2 + 0] + bias0[ni];
                    float v1 = c[mi][ni][hr * 2 + 1] + bias1[ni];
                    if (GEMM1) {
                        v0 = fmaxf(v0, 0.f);
                        v1 = fmaxf(v1, 0.f);
                        __half* hp = g_h + (size_t)slot * NDIM + f0 + col;
                        *(__half2*)hp = __floats2half2_rn(v0, v1);
                    } else {
                        float* op = g_so + (size_t)slot * NDIM + f0 + col;
                        float2 t;
                        t.x = v0;
                        t.y = v1;
                        *(float2*)op = t;
                    }
                }
            }
        }
    }
}

// ---------------------------------------------------------------------------
// combine: out[s,:] = w0[s]*so[s,:] + w1[s]*so[S+s,:]
// ---------------------------------------------------------------------------
__global__ void __launch_bounds__(256) combine_kernel(float* __restrict__ out) {
    int i4 = blockIdx.x * blockDim.x + threadIdx.x;
    const int N4 = S_TOK * DM / 4;
    if (i4 >= N4) return;
    int base = i4 * 4;
    int s = base / DM;
    float w0 = g_w[0][s];
    float w1 = g_w[1][s];
    float4 a = *(const float4*)(g_so + base);
    float4 b = *(const float4*)(g_so + (size_t)S_TOK * DM + base);
    float4 r;
    r.x = w0 * a.x + w1 * b.x;
    r.y = w0 * a.y + w1 * b.y;
    r.z = w0 * a.z + w1 * b.z;
    r.w = w0 * a.w + w1 * b.w;
    *(float4*)(out + base) = r;
}

// ---------------------------------------------------------------------------
extern "C" void kernel_launch(void* const* d_in, const int* in_sizes, int n_in,
                              void* d_out, int out_size) {
    const float* x  = (const float*)d_in[0];
    const float* Wg = (const float*)d_in[1];
    const float* W1 = (const float*)d_in[2];
    const float* b1 = (const float*)d_in[3];
    const float* W2 = (const float*)d_in[4];
    const float* b2 = (const float*)d_in[5];
    float* out = (float*)d_out;

    zero_counts_kernel<<<1, 32>>>();

    const int nx4 = S_TOK * DM / 4;
    const int nw4 = NE * DM * DF / 4;
    f2h_kernel<0><<<(nx4 + 255) / 256, 256>>>(x, nx4);
    f2h_kernel<1><<<(nw4 + 255) / 256, 256>>>(W1, nw4);
    f2h_kernel<2><<<(nw4 + 255) / 256, 256>>>(W2, nw4);

    gate_kernel<<<S_TOK / 8, 256>>>(x, Wg);

    moe_gemm<DM, DF, true ><<<dim3(DF / BN, NSLOT / BM, NE), 256>>>(b1);
    moe_gemm<DF, DM, false><<<dim3(DM / BN, NSLOT / BM, NE), 256>>>(b2);

    const int N4 = S_TOK * DM / 4;
    combine_kernel<<<(N4 + 255) / 256, 256>>>(out);
}

// round 4
// speedup vs baseline: 5.6144x; 1.4309x over previous
#include <cuda_runtime.h>
#include <cuda_fp16.h>

// Problem constants
#define S_TOK   4096
#define NSLOT   8192
#define DM      768
#define DF      3072
#define NE      8

#define BM 128
#define BN 128
#define BK 32
#define AS_STRIDE 56    // halves: 112B row (16B-aligned, conflict-free ldmatrix)
#define BS_STRIDE 136   // halves: 272B row (16B-aligned, conflict-free ldmatrix)

// ---- scratch (device globals; no allocation allowed) ----
__device__ int    g_count[NE];
__device__ int    g_list[NE][NSLOT];
__device__ float  g_w[2][S_TOK];
__device__ __half g_xh[(size_t)S_TOK * DM];
__device__ __half g_w1h[(size_t)NE * DM * DF];
__device__ __half g_w2h[(size_t)NE * DF * DM];
__device__ __half g_h[(size_t)NSLOT * DF];
__device__ float  g_so[(size_t)NSLOT * DM];

// ---------------------------------------------------------------------------
__global__ void zero_counts_kernel() {
    if (threadIdx.x < NE) g_count[threadIdx.x] = 0;
}

// ---------------------------------------------------------------------------
// float -> half converters (device-global destinations; DST tag selects)
// ---------------------------------------------------------------------------
template<int DST>
__global__ void __launch_bounds__(256) f2h_kernel(const float* __restrict__ src, int n4) {
    int i = blockIdx.x * blockDim.x + threadIdx.x;
    if (i >= n4) return;
    float4 v = ((const float4*)src)[i];
    __half2 a = __floats2half2_rn(v.x, v.y);
    __half2 b = __floats2half2_rn(v.z, v.w);
    uint2 pk;
    pk.x = *(unsigned int*)&a;
    pk.y = *(unsigned int*)&b;
    __half* dst = (DST == 0) ? g_xh : ((DST == 1) ? g_w1h : g_w2h);
    ((uint2*)dst)[i] = pk;
}

// ---------------------------------------------------------------------------
// gate: warp per token
// ---------------------------------------------------------------------------
__global__ void __launch_bounds__(256) gate_kernel(const float* __restrict__ x,
                                                   const float* __restrict__ Wg) {
    int warp = threadIdx.x >> 5;
    int lane = threadIdx.x & 31;
    int s = blockIdx.x * 8 + warp;
    if (s >= S_TOK) return;

    const float* xr = x + (size_t)s * DM;
    float acc[NE];
#pragma unroll
    for (int e = 0; e < NE; e++) acc[e] = 0.f;

    for (int m = lane; m < DM; m += 32) {
        float xv = xr[m];
        const float* wr = Wg + m * NE;
#pragma unroll
        for (int e = 0; e < NE; e++) acc[e] += xv * wr[e];
    }
#pragma unroll
    for (int e = 0; e < NE; e++) {
#pragma unroll
        for (int o = 16; o > 0; o >>= 1) {
            acc[e] += __shfl_xor_sync(0xffffffffu, acc[e], o);
        }
    }

    if (lane == 0) {
        int a = 0;
#pragma unroll
        for (int e = 1; e < NE; e++) {
            if (acc[e] > acc[a]) a = e;
        }
        int b = (a == 0) ? 1 : 0;
#pragma unroll
        for (int e = 0; e < NE; e++) {
            if (e != a && acc[e] > acc[b]) b = e;
        }

        float eb = __expf(acc[b] - acc[a]);
        float inv = 1.f / (1.f + eb);
        g_w[0][s] = inv;
        g_w[1][s] = eb * inv;

        int pa = atomicAdd(&g_count[a], 1);
        g_list[a][pa] = s;
        int pb = atomicAdd(&g_count[b], 1);
        g_list[b][pb] = S_TOK + s;
    }
}

// ---------------------------------------------------------------------------
// tensor-core + cp.async helpers
// ---------------------------------------------------------------------------
__device__ __forceinline__ void ldsm_x4(unsigned& r0, unsigned& r1,
                                        unsigned& r2, unsigned& r3,
                                        const void* p) {
    unsigned a = (unsigned)__cvta_generic_to_shared(p);
    asm volatile("ldmatrix.sync.aligned.m8n8.x4.shared.b16 {%0,%1,%2,%3}, [%4];\n"
                 : "=r"(r0), "=r"(r1), "=r"(r2), "=r"(r3) : "r"(a));
}

__device__ __forceinline__ void ldsm_x4_t(unsigned& r0, unsigned& r1,
                                          unsigned& r2, unsigned& r3,
                                          const void* p) {
    unsigned a = (unsigned)__cvta_generic_to_shared(p);
    asm volatile("ldmatrix.sync.aligned.m8n8.x4.trans.shared.b16 {%0,%1,%2,%3}, [%4];\n"
                 : "=r"(r0), "=r"(r1), "=r"(r2), "=r"(r3) : "r"(a));
}

__device__ __forceinline__ void mma16816(float* c, const unsigned* a, const unsigned* b) {
    asm volatile(
        "mma.sync.aligned.m16n8k16.row.col.f32.f16.f16.f32 "
        "{%0,%1,%2,%3}, {%4,%5,%6,%7}, {%8,%9}, {%0,%1,%2,%3};\n"
        : "+f"(c[0]), "+f"(c[1]), "+f"(c[2]), "+f"(c[3])
        : "r"(a[0]), "r"(a[1]), "r"(a[2]), "r"(a[3]), "r"(b[0]), "r"(b[1]));
}

// 16B async copy; src_size=0 zero-fills (used for invalid gather rows)
__device__ __forceinline__ void cp_async16(void* smem_ptr, const void* gptr, bool valid) {
    unsigned saddr = (unsigned)__cvta_generic_to_shared(smem_ptr);
    int sz = valid ? 16 : 0;
    asm volatile("cp.async.cg.shared.global [%0], [%1], 16, %2;\n"
                 :: "r"(saddr), "l"(gptr), "r"(sz));
}
__device__ __forceinline__ void cp_commit() {
    asm volatile("cp.async.commit_group;\n");
}
template<int N>
__device__ __forceinline__ void cp_wait() {
    asm volatile("cp.async.wait_group %0;\n" :: "n"(N));
}

// ---------------------------------------------------------------------------
// Grouped GEMM, double-buffered cp.async pipeline.
//   GEMM1: A = g_xh[slot & (S-1)], W = g_w1h, bias+relu -> g_h (half)
//   GEMM2: A = g_h[slot],          W = g_w2h, bias      -> g_so (float)
// grid (NDIM/BN, NSLOT/BM, NE), 256 threads (8 warps, 64x32 warp tiles)
// ---------------------------------------------------------------------------
template<int KDIM, int NDIM, bool GEMM1>
__global__ void __launch_bounds__(256) moe_gemm(const float* __restrict__ bias) {
    const int e = blockIdx.z;
    const int cnt = g_count[e];
    const int row0 = blockIdx.y * BM;
    if (row0 >= cnt) return;
    const int f0 = blockIdx.x * BN;

    __shared__ __half As[2][BM][AS_STRIDE];
    __shared__ __half Bs[2][BK][BS_STRIDE];
    __shared__ int rows_s[BM];

    const int tid = threadIdx.x;
    const int lane = tid & 31;
    const int wid = tid >> 5;
    const int wm = (wid >> 2) * 64;
    const int wn = (wid & 3) * 32;

    if (tid < BM) {
        int r = row0 + tid;
        rows_s[tid] = (r < cnt) ? g_list[e][r] : -1;
    }
    __syncthreads();

    const __half* Ab = GEMM1 ? g_xh : g_h;
    const __half* Wb = (GEMM1 ? g_w1h : g_w2h) + (size_t)e * KDIM * NDIM;

    // per-thread load coordinates (2 A chunks + 2 B chunks per stage)
    // A: u in [0,512): r = u>>2, kq = u&3 (8 halves each)
    // B: u in [0,512): kr = u>>4, cq = u&15
    int a_r[2], a_kq[2], a_slot[2];
    int b_kr[2], b_cq[2];
#pragma unroll
    for (int l = 0; l < 2; l++) {
        int u = tid + l * 256;
        a_r[l] = u >> 2;
        a_kq[l] = u & 3;
        a_slot[l] = rows_s[a_r[l]];
        b_kr[l] = u >> 4;
        b_cq[l] = u & 15;
    }

    const int NK = KDIM / BK;

    // ---- pipeline load helper (macro-free lambda) ----
    auto load_tile = [&](int buf, int kt) {
#pragma unroll
        for (int l = 0; l < 2; l++) {
            int slot = a_slot[l];
            const __half* src = Ab;
            if (slot >= 0) {
                int arow = GEMM1 ? (slot & (S_TOK - 1)) : slot;
                src = Ab + (size_t)arow * KDIM + kt + a_kq[l] * 8;
            }
            cp_async16(&As[buf][a_r[l]][a_kq[l] * 8], src, slot >= 0);
        }
#pragma unroll
        for (int l = 0; l < 2; l++) {
            const __half* src = Wb + (size_t)(kt + b_kr[l]) * NDIM + f0 + b_cq[l] * 8;
            cp_async16(&Bs[buf][b_kr[l]][b_cq[l] * 8], src, true);
        }
    };

    float c[4][4][4];
#pragma unroll
    for (int mi = 0; mi < 4; mi++) {
#pragma unroll
        for (int ni = 0; ni < 4; ni++) {
#pragma unroll
            for (int q = 0; q < 4; q++) {
                c[mi][ni][q] = 0.f;
            }
        }
    }

    load_tile(0, 0);
    cp_commit();

    for (int k = 0; k < NK; k++) {
        if (k + 1 < NK) {
            load_tile((k + 1) & 1, (k + 1) * BK);
        }
        cp_commit();
        cp_wait<1>();
        __syncthreads();

        const int buf = k & 1;
#pragma unroll
        for (int kc = 0; kc < BK; kc += 16) {
            unsigned af[4][4];
            unsigned bf[4][2];
#pragma unroll
            for (int mi = 0; mi < 4; mi++) {
                ldsm_x4(af[mi][0], af[mi][1], af[mi][2], af[mi][3],
                        &As[buf][wm + mi * 16 + (lane & 15)][kc + (lane >> 4) * 8]);
            }
#pragma unroll
            for (int nj = 0; nj < 2; nj++) {
                ldsm_x4_t(bf[2 * nj][0], bf[2 * nj][1],
                          bf[2 * nj + 1][0], bf[2 * nj + 1][1],
                          &Bs[buf][kc + (lane & 15)][wn + nj * 16 + (lane >> 4) * 8]);
            }
#pragma unroll
            for (int mi = 0; mi < 4; mi++) {
#pragma unroll
                for (int ni = 0; ni < 4; ni++) {
                    mma16816(c[mi][ni], af[mi], bf[ni]);
                }
            }
        }
        __syncthreads();
    }

    // epilogue
    const float* be = bias + (size_t)e * NDIM + f0;
    float bias0[4];
    float bias1[4];
#pragma unroll
    for (int ni = 0; ni < 4; ni++) {
        int col = wn + ni * 8 + (lane & 3) * 2;
        bias0[ni] = be[col];
        bias1[ni] = be[col + 1];
    }
#pragma unroll
    for (int mi = 0; mi < 4; mi++) {
#pragma unroll
        for (int hr = 0; hr < 2; hr++) {
            int rr = wm + mi * 16 + hr * 8 + (lane >> 2);
            int slot = rows_s[rr];
            if (slot >= 0) {
#pragma unroll
                for (int ni = 0; ni < 4; ni++) {
                    int col = wn + ni * 8 + (lane & 3) * 2;
                    float v0 = c[mi][ni][hr * 2 + 0] + bias0[ni];
                    float v1 = c[mi][ni][hr * 2 + 1] + bias1[ni];
                    if (GEMM1) {
                        v0 = fmaxf(v0, 0.f);
                        v1 = fmaxf(v1, 0.f);
                        __half* hp = g_h + (size_t)slot * NDIM + f0 + col;
                        *(__half2*)hp = __floats2half2_rn(v0, v1);
                    } else {
                        float* op = g_so + (size_t)slot * NDIM + f0 + col;
                        float2 t;
                        t.x = v0;
                        t.y = v1;
                        *(float2*)op = t;
                    }
                }
            }
        }
    }
}

// ---------------------------------------------------------------------------
// combine: out[s,:] = w0[s]*so[s,:] + w1[s]*so[S+s,:]
// ---------------------------------------------------------------------------
__global__ void __launch_bounds__(256) combine_kernel(float* __restrict__ out) {
    int i4 = blockIdx.x * blockDim.x + threadIdx.x;
    const int N4 = S_TOK * DM / 4;
    if (i4 >= N4) return;
    int base = i4 * 4;
    int s = base / DM;
    float w0 = g_w[0][s];
    float w1 = g_w[1][s];
    float4 a = *(const float4*)(g_so + base);
    float4 b = *(const float4*)(g_so + (size_t)S_TOK * DM + base);
    float4 r;
    r.x = w0 * a.x + w1 * b.x;
    r.y = w0 * a.y + w1 * b.y;
    r.z = w0 * a.z + w1 * b.z;
    r.w = w0 * a.w + w1 * b.w;
    *(float4*)(out + base) = r;
}

// ---------------------------------------------------------------------------
extern "C" void kernel_launch(void* const* d_in, const int* in_sizes, int n_in,
                              void* d_out, int out_size) {
    const float* x  = (const float*)d_in[0];
    const float* Wg = (const float*)d_in[1];
    const float* W1 = (const float*)d_in[2];
    const float* b1 = (const float*)d_in[3];
    const float* W2 = (const float*)d_in[4];
    const float* b2 = (const float*)d_in[5];
    float* out = (float*)d_out;

    zero_counts_kernel<<<1, 32>>>();

    const int nx4 = S_TOK * DM / 4;
    const int nw4 = NE * DM * DF / 4;
    f2h_kernel<0><<<(nx4 + 255) / 256, 256>>>(x, nx4);
    f2h_kernel<1><<<(nw4 + 255) / 256, 256>>>(W1, nw4);
    f2h_kernel<2><<<(nw4 + 255) / 256, 256>>>(W2, nw4);

    gate_kernel<<<S_TOK / 8, 256>>>(x, Wg);

    moe_gemm<DM, DF, true ><<<dim3(DF / BN, NSLOT / BM, NE), 256>>>(b1);
    moe_gemm<DF, DM, false><<<dim3(DM / BN, NSLOT / BM, NE), 256>>>(b2);

    const int N4 = S_TOK * DM / 4;
    combine_kernel<<<(N4 + 255) / 256, 256>>>(out);
}

// round 6
// speedup vs baseline: 5.6463x; 1.0057x over previous
#include <cuda_runtime.h>
#include <cuda_fp16.h>
#include <cstdint>

// Problem constants
#define S_TOK   4096
#define NSLOT   8192
#define DM      768
#define DF      3072
#define NE      8

#define BM 128
#define BK 32
#define STAGES 3
#define ASTR 40            // A smem stride in halves (80B rows, conflict-free ldmatrix)

// ---- scratch (device globals; no allocation allowed) ----
__device__ int    g_count[NE];
__device__ int    g_list[NE][NSLOT];
__device__ float  g_w[2][S_TOK];
__device__ __half g_xh[(size_t)S_TOK * DM];
__device__ __half g_w1h[(size_t)NE * DM * DF];
__device__ __half g_w2h[(size_t)NE * DF * DM];
__device__ __half g_h[(size_t)NSLOT * DF];
__device__ float  g_so[(size_t)NSLOT * DM];

// ---------------------------------------------------------------------------
__global__ void zero_counts_kernel() {
    if (threadIdx.x < NE) g_count[threadIdx.x] = 0;
}

// ---------------------------------------------------------------------------
// float -> half converters (device-global destinations; DST tag selects)
// ---------------------------------------------------------------------------
template<int DST>
__global__ void __launch_bounds__(256) f2h_kernel(const float* __restrict__ src, int n4) {
    int i = blockIdx.x * blockDim.x + threadIdx.x;
    if (i >= n4) return;
    float4 v = ((const float4*)src)[i];
    __half2 a = __floats2half2_rn(v.x, v.y);
    __half2 b = __floats2half2_rn(v.z, v.w);
    uint2 pk;
    pk.x = *(unsigned int*)&a;
    pk.y = *(unsigned int*)&b;
    __half* dst = (DST == 0) ? g_xh : ((DST == 1) ? g_w1h : g_w2h);
    ((uint2*)dst)[i] = pk;
}

// ---------------------------------------------------------------------------
// gate: warp per token
// ---------------------------------------------------------------------------
__global__ void __launch_bounds__(256) gate_kernel(const float* __restrict__ x,
                                                   const float* __restrict__ Wg) {
    int warp = threadIdx.x >> 5;
    int lane = threadIdx.x & 31;
    int s = blockIdx.x * 8 + warp;
    if (s >= S_TOK) return;

    const float* xr = x + (size_t)s * DM;
    float acc[NE];
#pragma unroll
    for (int e = 0; e < NE; e++) acc[e] = 0.f;

    for (int m = lane; m < DM; m += 32) {
        float xv = xr[m];
        const float* wr = Wg + m * NE;
#pragma unroll
        for (int e = 0; e < NE; e++) acc[e] += xv * wr[e];
    }
#pragma unroll
    for (int e = 0; e < NE; e++) {
#pragma unroll
        for (int o = 16; o > 0; o >>= 1) {
            acc[e] += __shfl_xor_sync(0xffffffffu, acc[e], o);
        }
    }

    if (lane == 0) {
        int a = 0;
#pragma unroll
        for (int e = 1; e < NE; e++) {
            if (acc[e] > acc[a]) a = e;
        }
        int b = (a == 0) ? 1 : 0;
#pragma unroll
        for (int e = 0; e < NE; e++) {
            if (e != a && acc[e] > acc[b]) b = e;
        }

        float eb = __expf(acc[b] - acc[a]);
        float inv = 1.f / (1.f + eb);
        g_w[0][s] = inv;
        g_w[1][s] = eb * inv;

        int pa = atomicAdd(&g_count[a], 1);
        g_list[a][pa] = s;
        int pb = atomicAdd(&g_count[b], 1);
        g_list[b][pb] = S_TOK + s;
    }
}

// ---------------------------------------------------------------------------
// tensor-core + cp.async helpers
// ---------------------------------------------------------------------------
__device__ __forceinline__ void ldsm_x4(unsigned& r0, unsigned& r1,
                                        unsigned& r2, unsigned& r3,
                                        const void* p) {
    unsigned a = (unsigned)__cvta_generic_to_shared(p);
    asm volatile("ldmatrix.sync.aligned.m8n8.x4.shared.b16 {%0,%1,%2,%3}, [%4];\n"
                 : "=r"(r0), "=r"(r1), "=r"(r2), "=r"(r3) : "r"(a));
}

__device__ __forceinline__ void ldsm_x4_t(unsigned& r0, unsigned& r1,
                                          unsigned& r2, unsigned& r3,
                                          const void* p) {
    unsigned a = (unsigned)__cvta_generic_to_shared(p);
    asm volatile("ldmatrix.sync.aligned.m8n8.x4.trans.shared.b16 {%0,%1,%2,%3}, [%4];\n"
                 : "=r"(r0), "=r"(r1), "=r"(r2), "=r"(r3) : "r"(a));
}

__device__ __forceinline__ void mma16816(float* c, const unsigned* a, const unsigned* b) {
    asm volatile(
        "mma.sync.aligned.m16n8k16.row.col.f32.f16.f16.f32 "
        "{%0,%1,%2,%3}, {%4,%5,%6,%7}, {%8,%9}, {%0,%1,%2,%3};\n"
        : "+f"(c[0]), "+f"(c[1]), "+f"(c[2]), "+f"(c[3])
        : "r"(a[0]), "r"(a[1]), "r"(a[2]), "r"(a[3]), "r"(b[0]), "r"(b[1]));
}

__device__ __forceinline__ void cp_async16(void* smem_ptr, const void* gptr, bool valid) {
    unsigned saddr = (unsigned)__cvta_generic_to_shared(smem_ptr);
    int sz = valid ? 16 : 0;
    asm volatile("cp.async.cg.shared.global [%0], [%1], 16, %2;\n"
                 :: "r"(saddr), "l"(gptr), "r"(sz));
}
__device__ __forceinline__ void cp_commit() {
    asm volatile("cp.async.commit_group;\n");
}
template<int N>
__device__ __forceinline__ void cp_wait() {
    asm volatile("cp.async.wait_group %0;\n" :: "n"(N));
}

// ---------------------------------------------------------------------------
// Grouped GEMM, 3-stage cp.async pipeline, templated tile width.
//   GEMM1: BN=256 (warp 64x64): A = g_xh[slot & (S-1)], W = g_w1h -> relu -> g_h (half)
//   GEMM2: BN=128 (warp 64x32): A = g_h[slot],          W = g_w2h          -> g_so (float)
// grid (NDIM/BN_, NSLOT/BM, NE), 256 threads (8 warps, 2x4 warp grid)
// ---------------------------------------------------------------------------
template<int KDIM, int NDIM, int BN_, bool GEMM1>
__global__ void __launch_bounds__(256) moe_gemm(const float* __restrict__ bias) {
    constexpr int WN = BN_ / 4;        // warp N extent (64 or 32)
    constexpr int NF = WN / 8;         // n8 fragments per warp (8 or 4)
    constexpr int BSTR = BN_ + 8;      // B smem stride in halves
    constexpr int A_ST_ELEM = BM * ASTR;          // halves per A stage
    constexpr int B_ST_ELEM = BK * BSTR;          // halves per B stage
    constexpr int B_CHUNKS_PT = BN_ / 64;         // B 16B-chunks per thread (4 or 2)

    const int e = blockIdx.z;
    const int cnt = g_count[e];
    const int row0 = blockIdx.y * BM;
    if (row0 >= cnt) return;
    const int f0 = blockIdx.x * BN_;

    extern __shared__ __half dyn[];
    __half* Asb = dyn;                           // [STAGES][BM][ASTR]
    __half* Bsb = dyn + STAGES * A_ST_ELEM;      // [STAGES][BK][BSTR]
    __shared__ int rows_s[BM];

    const int tid = threadIdx.x;
    const int lane = tid & 31;
    const int wid = tid >> 5;
    const int wm = (wid >> 2) * 64;
    const int wn = (wid & 3) * WN;

    if (tid < BM) {
        int r = row0 + tid;
        rows_s[tid] = (r < cnt) ? g_list[e][r] : -1;
    }
    __syncthreads();

    const __half* Ab = GEMM1 ? g_xh : g_h;
    const __half* Wb = (GEMM1 ? g_w1h : g_w2h) + (size_t)e * KDIM * NDIM;

    // per-thread load coords
    // A: 512 chunks (128 rows x 4 chunks); 2 per thread
    int a_r[2], a_kq[2], a_slot[2];
#pragma unroll
    for (int l = 0; l < 2; l++) {
        int u = tid + l * 256;
        a_r[l] = u >> 2;
        a_kq[l] = u & 3;
        a_slot[l] = rows_s[a_r[l]];
    }
    // B: BK rows x BN_/8 chunks; B_CHUNKS_PT per thread
    int b_kr[B_CHUNKS_PT], b_cq[B_CHUNKS_PT];
#pragma unroll
    for (int l = 0; l < B_CHUNKS_PT; l++) {
        int u = tid + l * 256;
        if (BN_ == 256) {
            b_kr[l] = u >> 5;
            b_cq[l] = u & 31;
        } else {
            b_kr[l] = u >> 4;
            b_cq[l] = u & 15;
        }
    }

    const int NK = KDIM / BK;

    auto load_tile = [&](int buf, int kt) {
        __half* As = Asb + buf * A_ST_ELEM;
        __half* Bs = Bsb + buf * B_ST_ELEM;
#pragma unroll
        for (int l = 0; l < 2; l++) {
            int slot = a_slot[l];
            const __half* src = Ab;
            bool v = (slot >= 0);
            if (v) {
                int arow = GEMM1 ? (slot & (S_TOK - 1)) : slot;
                src = Ab + (size_t)arow * KDIM + kt + a_kq[l] * 8;
            }
            cp_async16(As + a_r[l] * ASTR + a_kq[l] * 8, src, v);
        }
#pragma unroll
        for (int l = 0; l < B_CHUNKS_PT; l++) {
            const __half* src = Wb + (size_t)(kt + b_kr[l]) * NDIM + f0 + b_cq[l] * 8;
            cp_async16(Bs + b_kr[l] * BSTR + b_cq[l] * 8, src, true);
        }
    };

    float c[4][NF][4];
#pragma unroll
    for (int mi = 0; mi < 4; mi++) {
#pragma unroll
        for (int ni = 0; ni < NF; ni++) {
#pragma unroll
            for (int q = 0; q < 4; q++) {
                c[mi][ni][q] = 0.f;
            }
        }
    }

    load_tile(0, 0);
    cp_commit();
    load_tile(1, BK);
    cp_commit();

    for (int k = 0; k < NK; k++) {
        cp_wait<1>();
        __syncthreads();

        if (k + 2 < NK) {
            load_tile((k + 2) % STAGES, (k + 2) * BK);
        }
        cp_commit();

        const int buf = k % STAGES;
        const __half* As = Asb + buf * A_ST_ELEM;
        const __half* Bs = Bsb + buf * B_ST_ELEM;
#pragma unroll
        for (int kc = 0; kc < BK; kc += 16) {
            unsigned af[4][4];
            unsigned bf[NF][2];
#pragma unroll
            for (int mi = 0; mi < 4; mi++) {
                ldsm_x4(af[mi][0], af[mi][1], af[mi][2], af[mi][3],
                        As + (wm + mi * 16 + (lane & 15)) * ASTR + kc + (lane >> 4) * 8);
            }
#pragma unroll
            for (int nj = 0; nj < NF / 2; nj++) {
                ldsm_x4_t(bf[2 * nj][0], bf[2 * nj][1],
                          bf[2 * nj + 1][0], bf[2 * nj + 1][1],
                          Bs + (kc + (lane & 15)) * BSTR + wn + nj * 16 + (lane >> 4) * 8);
            }
#pragma unroll
            for (int mi = 0; mi < 4; mi++) {
#pragma unroll
                for (int ni = 0; ni < NF; ni++) {
                    mma16816(c[mi][ni], af[mi], bf[ni]);
                }
            }
        }
    }

    // epilogue
    const float* be = bias + (size_t)e * NDIM + f0;
    float bias0[NF];
    float bias1[NF];
#pragma unroll
    for (int ni = 0; ni < NF; ni++) {
        int col = wn + ni * 8 + (lane & 3) * 2;
        bias0[ni] = be[col];
        bias1[ni] = be[col + 1];
    }
#pragma unroll
    for (int mi = 0; mi < 4; mi++) {
#pragma unroll
        for (int hr = 0; hr < 2; hr++) {
            int rr = wm + mi * 16 + hr * 8 + (lane >> 2);
            int slot = rows_s[rr];
            if (slot >= 0) {
#pragma unroll
                for (int ni = 0; ni < NF; ni++) {
                    int col = wn + ni * 8 + (lane & 3) * 2;
                    float v0 = c[mi][ni][hr * 2 + 0] + bias0[ni];
                    float v1 = c[mi][ni][hr * 2 + 1] + bias1[ni];
                    if (GEMM1) {
                        v0 = fmaxf(v0, 0.f);
                        v1 = fmaxf(v1, 0.f);
                        __half* hp = g_h + (size_t)slot * NDIM + f0 + col;
                        *(__half2*)hp = __floats2half2_rn(v0, v1);
                    } else {
                        float* op = g_so + (size_t)slot * NDIM + f0 + col;
                        float2 t;
                        t.x = v0;
                        t.y = v1;
                        *(float2*)op = t;
                    }
                }
            }
        }
    }
}

// ---------------------------------------------------------------------------
// combine: out[s,:] = w0[s]*so[s,:] + w1[s]*so[S+s,:]
// ---------------------------------------------------------------------------
__global__ void __launch_bounds__(256) combine_kernel(float* __restrict__ out) {
    int i4 = blockIdx.x * blockDim.x + threadIdx.x;
    const int N4 = S_TOK * DM / 4;
    if (i4 >= N4) return;
    int base = i4 * 4;
    int s = base / DM;
    float w0 = g_w[0][s];
    float w1 = g_w[1][s];
    float4 a = *(const float4*)(g_so + base);
    float4 b = *(const float4*)(g_so + (size_t)S_TOK * DM + base);
    float4 r;
    r.x = w0 * a.x + w1 * b.x;
    r.y = w0 * a.y + w1 * b.y;
    r.z = w0 * a.z + w1 * b.z;
    r.w = w0 * a.w + w1 * b.w;
    *(float4*)(out + base) = r;
}

// ---------------------------------------------------------------------------
extern "C" void kernel_launch(void* const* d_in, const int* in_sizes, int n_in,
                              void* d_out, int out_size) {
    const float* x  = (const float*)d_in[0];
    const float* Wg = (const float*)d_in[1];
    const float* W1 = (const float*)d_in[2];
    const float* b1 = (const float*)d_in[3];
    const float* W2 = (const float*)d_in[4];
    const float* b2 = (const float*)d_in[5];
    float* out = (float*)d_out;

    // dynamic smem sizes (halves -> bytes)
    const int smem1 = (STAGES * (BM * ASTR + BK * (256 + 8))) * 2;
    const int smem2 = (STAGES * (BM * ASTR + BK * (128 + 8))) * 2;
    cudaFuncSetAttribute(moe_gemm<DM, DF, 256, true>,
                         cudaFuncAttributeMaxDynamicSharedMemorySize, smem1);
    cudaFuncSetAttribute(moe_gemm<DF, DM, 128, false>,
                         cudaFuncAttributeMaxDynamicSharedMemorySize, smem2);

    zero_counts_kernel<<<1, 32>>>();

    const int nx4 = S_TOK * DM / 4;
    const int nw4 = NE * DM * DF / 4;
    f2h_kernel<0><<<(nx4 + 255) / 256, 256>>>(x, nx4);
    f2h_kernel<1><<<(nw4 + 255) / 256, 256>>>(W1, nw4);
    f2h_kernel<2><<<(nw4 + 255) / 256, 256>>>(W2, nw4);

    gate_kernel<<<S_TOK / 8, 256>>>(x, Wg);

    moe_gemm<DM, DF, 256, true ><<<dim3(DF / 256, NSLOT / BM, NE), 256, smem1>>>(b1);
    moe_gemm<DF, DM, 128, false><<<dim3(DM / 128, NSLOT / BM, NE), 256, smem2>>>(b2);

    const int N4 = S_TOK * DM / 4;
    combine_kernel<<<(N4 + 255) / 256, 256>>>(out);
}

// round 7
// speedup vs baseline: 6.3654x; 1.1274x over previous
#include <cuda_runtime.h>
#include <cuda_fp16.h>
#include <cstdint>

// Problem constants
#define S_TOK   4096
#define NSLOT   8192
#define DM      768
#define DF      3072
#define NE      8

#define BM 128
#define BK 64
#define ASTR 72            // A smem stride in halves (144B rows; 16r mod 128 distinct banks)

// ---- scratch (device globals; no allocation allowed) ----
__device__ int    g_count[NE];
__device__ int    g_list[NE][NSLOT];
__device__ float  g_sw[NSLOT];                    // per-slot combine weight
__device__ __half g_xh[(size_t)S_TOK * DM];
__device__ __half g_w1h[(size_t)NE * DM * DF];
__device__ __half g_w2h[(size_t)NE * DF * DM];
__device__ __half g_h[(size_t)NSLOT * DF];

// ---------------------------------------------------------------------------
// prep: zero out + zero counts + all three f2h converts, one launch
// ---------------------------------------------------------------------------
#define N_OUT4 (S_TOK * DM / 4)
#define NX4    (S_TOK * DM / 4)
#define NW4    (NE * DM * DF / 4)
#define PREP_ITEMS (N_OUT4 + NX4 + 2 * NW4)

__device__ __forceinline__ uint2 cvt4(const float4 v) {
    __half2 a = __floats2half2_rn(v.x, v.y);
    __half2 b = __floats2half2_rn(v.z, v.w);
    uint2 pk;
    pk.x = *(const unsigned*)&a;
    pk.y = *(const unsigned*)&b;
    return pk;
}

__global__ void __launch_bounds__(256) prep_kernel(float* __restrict__ out,
                                                   const float* __restrict__ x,
                                                   const float* __restrict__ W1,
                                                   const float* __restrict__ W2) {
    int i = blockIdx.x * blockDim.x + threadIdx.x;
    if (blockIdx.x == 0 && threadIdx.x < NE) g_count[threadIdx.x] = 0;
    if (i < N_OUT4) {
        ((float4*)out)[i] = make_float4(0.f, 0.f, 0.f, 0.f);
        return;
    }
    i -= N_OUT4;
    if (i < NX4) {
        ((uint2*)g_xh)[i] = cvt4(((const float4*)x)[i]);
        return;
    }
    i -= NX4;
    if (i < NW4) {
        ((uint2*)g_w1h)[i] = cvt4(((const float4*)W1)[i]);
        return;
    }
    i -= NW4;
    if (i < NW4) {
        ((uint2*)g_w2h)[i] = cvt4(((const float4*)W2)[i]);
    }
}

// ---------------------------------------------------------------------------
// gate: warp per token
// ---------------------------------------------------------------------------
__global__ void __launch_bounds__(256) gate_kernel(const float* __restrict__ x,
                                                   const float* __restrict__ Wg) {
    int warp = threadIdx.x >> 5;
    int lane = threadIdx.x & 31;
    int s = blockIdx.x * 8 + warp;
    if (s >= S_TOK) return;

    const float* xr = x + (size_t)s * DM;
    float acc[NE];
#pragma unroll
    for (int e = 0; e < NE; e++) acc[e] = 0.f;

    for (int m = lane; m < DM; m += 32) {
        float xv = xr[m];
        const float* wr = Wg + m * NE;
#pragma unroll
        for (int e = 0; e < NE; e++) acc[e] += xv * wr[e];
    }
#pragma unroll
    for (int e = 0; e < NE; e++) {
#pragma unroll
        for (int o = 16; o > 0; o >>= 1) {
            acc[e] += __shfl_xor_sync(0xffffffffu, acc[e], o);
        }
    }

    if (lane == 0) {
        int a = 0;
#pragma unroll
        for (int e = 1; e < NE; e++) {
            if (acc[e] > acc[a]) a = e;
        }
        int b = (a == 0) ? 1 : 0;
#pragma unroll
        for (int e = 0; e < NE; e++) {
            if (e != a && acc[e] > acc[b]) b = e;
        }

        float eb = __expf(acc[b] - acc[a]);
        float inv = 1.f / (1.f + eb);
        g_sw[s] = inv;
        g_sw[S_TOK + s] = eb * inv;

        int pa = atomicAdd(&g_count[a], 1);
        g_list[a][pa] = s;
        int pb = atomicAdd(&g_count[b], 1);
        g_list[b][pb] = S_TOK + s;
    }
}

// ---------------------------------------------------------------------------
// tensor-core + cp.async helpers
// ---------------------------------------------------------------------------
__device__ __forceinline__ void ldsm_x4(unsigned& r0, unsigned& r1,
                                        unsigned& r2, unsigned& r3,
                                        const void* p) {
    unsigned a = (unsigned)__cvta_generic_to_shared(p);
    asm volatile("ldmatrix.sync.aligned.m8n8.x4.shared.b16 {%0,%1,%2,%3}, [%4];\n"
                 : "=r"(r0), "=r"(r1), "=r"(r2), "=r"(r3) : "r"(a));
}

__device__ __forceinline__ void ldsm_x4_t(unsigned& r0, unsigned& r1,
                                          unsigned& r2, unsigned& r3,
                                          const void* p) {
    unsigned a = (unsigned)__cvta_generic_to_shared(p);
    asm volatile("ldmatrix.sync.aligned.m8n8.x4.trans.shared.b16 {%0,%1,%2,%3}, [%4];\n"
                 : "=r"(r0), "=r"(r1), "=r"(r2), "=r"(r3) : "r"(a));
}

__device__ __forceinline__ void mma16816(float* c, const unsigned* a, const unsigned* b) {
    asm volatile(
        "mma.sync.aligned.m16n8k16.row.col.f32.f16.f16.f32 "
        "{%0,%1,%2,%3}, {%4,%5,%6,%7}, {%8,%9}, {%0,%1,%2,%3};\n"
        : "+f"(c[0]), "+f"(c[1]), "+f"(c[2]), "+f"(c[3])
        : "r"(a[0]), "r"(a[1]), "r"(a[2]), "r"(a[3]), "r"(b[0]), "r"(b[1]));
}

__device__ __forceinline__ void cp_async16(void* smem_ptr, const void* gptr, bool valid) {
    unsigned saddr = (unsigned)__cvta_generic_to_shared(smem_ptr);
    int sz = valid ? 16 : 0;
    asm volatile("cp.async.cg.shared.global [%0], [%1], 16, %2;\n"
                 :: "r"(saddr), "l"(gptr), "r"(sz));
}
__device__ __forceinline__ void cp_commit() {
    asm volatile("cp.async.commit_group;\n");
}
template<int N>
__device__ __forceinline__ void cp_wait() {
    asm volatile("cp.async.wait_group %0;\n" :: "n"(N));
}

// ---------------------------------------------------------------------------
// Grouped GEMM, 2-stage BK=64 cp.async pipeline.
//   GEMM1: BN=256 (warp 64x64): A = g_xh[slot & (S-1)], W = g_w1h -> relu -> g_h (half)
//   GEMM2: BN=128 (warp 64x32): A = g_h[slot], W = g_w2h -> w*(.+b2) atomicAdd -> out
// grid (NDIM/BN_, NSLOT/BM, NE), 256 threads (8 warps, 2x4 warp grid)
// ---------------------------------------------------------------------------
template<int KDIM, int NDIM, int BN_, bool GEMM1, int MINB>
__global__ void __launch_bounds__(256, MINB) moe_gemm(const float* __restrict__ bias,
                                                      float* __restrict__ out) {
    constexpr int WN = BN_ / 4;
    constexpr int NF = WN / 8;
    constexpr int BSTR = BN_ + 8;
    constexpr int A_ST_ELEM = BM * ASTR;
    constexpr int B_ST_ELEM = BK * BSTR;
    constexpr int A_CH_PT = (BM * BK / 8) / 256;     // 4
    constexpr int B_CH_PT = (BK * BN_ / 8) / 256;    // 8 or 4

    const int e = blockIdx.z;
    const int cnt = g_count[e];
    const int row0 = blockIdx.y * BM;
    if (row0 >= cnt) return;
    const int f0 = blockIdx.x * BN_;

    extern __shared__ __half dyn[];
    __half* Asb = dyn;                        // [2][BM][ASTR]
    __half* Bsb = dyn + 2 * A_ST_ELEM;        // [2][BK][BSTR]
    __shared__ int rows_s[BM];

    const int tid = threadIdx.x;
    const int lane = tid & 31;
    const int wid = tid >> 5;
    const int wm = (wid >> 2) * 64;
    const int wn = (wid & 3) * WN;

    if (tid < BM) {
        int r = row0 + tid;
        rows_s[tid] = (r < cnt) ? g_list[e][r] : -1;
    }
    __syncthreads();

    const __half* Ab = GEMM1 ? g_xh : g_h;
    const __half* Wb = (GEMM1 ? g_w1h : g_w2h) + (size_t)e * KDIM * NDIM;

    // per-thread load coords
    int a_r[A_CH_PT], a_kq[A_CH_PT], a_slot[A_CH_PT];
#pragma unroll
    for (int l = 0; l < A_CH_PT; l++) {
        int u = tid + l * 256;
        a_r[l] = u >> 3;
        a_kq[l] = u & 7;
        a_slot[l] = rows_s[a_r[l]];
    }
    int b_kr[B_CH_PT], b_cq[B_CH_PT];
#pragma unroll
    for (int l = 0; l < B_CH_PT; l++) {
        int u = tid + l * 256;
        if (BN_ == 256) {
            b_kr[l] = u >> 5;
            b_cq[l] = u & 31;
        } else {
            b_kr[l] = u >> 4;
            b_cq[l] = u & 15;
        }
    }

    const int NK = KDIM / BK;

    auto load_tile = [&](int buf, int kt) {
        __half* As = Asb + buf * A_ST_ELEM;
        __half* Bs = Bsb + buf * B_ST_ELEM;
#pragma unroll
        for (int l = 0; l < A_CH_PT; l++) {
            int slot = a_slot[l];
            const __half* src = Ab;
            bool v = (slot >= 0);
            if (v) {
                int arow = GEMM1 ? (slot & (S_TOK - 1)) : slot;
                src = Ab + (size_t)arow * KDIM + kt + a_kq[l] * 8;
            }
            cp_async16(As + a_r[l] * ASTR + a_kq[l] * 8, src, v);
        }
#pragma unroll
        for (int l = 0; l < B_CH_PT; l++) {
            const __half* src = Wb + (size_t)(kt + b_kr[l]) * NDIM + f0 + b_cq[l] * 8;
            cp_async16(Bs + b_kr[l] * BSTR + b_cq[l] * 8, src, true);
        }
    };

    float c[4][NF][4];
#pragma unroll
    for (int mi = 0; mi < 4; mi++) {
#pragma unroll
        for (int ni = 0; ni < NF; ni++) {
#pragma unroll
            for (int q = 0; q < 4; q++) {
                c[mi][ni][q] = 0.f;
            }
        }
    }

    load_tile(0, 0);
    cp_commit();

    for (int k = 0; k < NK; k++) {
        cp_wait<0>();
        __syncthreads();        // tile k visible; everyone done with compute k-1

        if (k + 1 < NK) {
            load_tile((k + 1) & 1, (k + 1) * BK);   // overwrites buffer of tile k-1 (safe)
            cp_commit();
        }

        const int buf = k & 1;
        const __half* As = Asb + buf * A_ST_ELEM;
        const __half* Bs = Bsb + buf * B_ST_ELEM;
#pragma unroll
        for (int kc = 0; kc < BK; kc += 16) {
            unsigned af[4][4];
            unsigned bf[NF][2];
#pragma unroll
            for (int mi = 0; mi < 4; mi++) {
                ldsm_x4(af[mi][0], af[mi][1], af[mi][2], af[mi][3],
                        As + (wm + mi * 16 + (lane & 15)) * ASTR + kc + (lane >> 4) * 8);
            }
#pragma unroll
            for (int nj = 0; nj < NF / 2; nj++) {
                ldsm_x4_t(bf[2 * nj][0], bf[2 * nj][1],
                          bf[2 * nj + 1][0], bf[2 * nj + 1][1],
                          Bs + (kc + (lane & 15)) * BSTR + wn + nj * 16 + (lane >> 4) * 8);
            }
#pragma unroll
            for (int mi = 0; mi < 4; mi++) {
#pragma unroll
                for (int ni = 0; ni < NF; ni++) {
                    mma16816(c[mi][ni], af[mi], bf[ni]);
                }
            }
        }
    }

    // epilogue
    const float* be = bias + (size_t)e * NDIM + f0;
    float bias0[NF];
    float bias1[NF];
#pragma unroll
    for (int ni = 0; ni < NF; ni++) {
        int col = wn + ni * 8 + (lane & 3) * 2;
        bias0[ni] = be[col];
        bias1[ni] = be[col + 1];
    }
#pragma unroll
    for (int mi = 0; mi < 4; mi++) {
#pragma unroll
        for (int hr = 0; hr < 2; hr++) {
            int rr = wm + mi * 16 + hr * 8 + (lane >> 2);
            int slot = rows_s[rr];
            if (slot >= 0) {
                if (GEMM1) {
                    __half* hp = g_h + (size_t)slot * NDIM + f0;
#pragma unroll
                    for (int ni = 0; ni < NF; ni++) {
                        int col = wn + ni * 8 + (lane & 3) * 2;
                        float v0 = fmaxf(c[mi][ni][hr * 2 + 0] + bias0[ni], 0.f);
                        float v1 = fmaxf(c[mi][ni][hr * 2 + 1] + bias1[ni], 0.f);
                        *(__half2*)(hp + col) = __floats2half2_rn(v0, v1);
                    }
                } else {
                    int tok = slot & (S_TOK - 1);
                    float w = g_sw[slot];
                    float* op = out + (size_t)tok * DM + f0;
#pragma unroll
                    for (int ni = 0; ni < NF; ni++) {
                        int col = wn + ni * 8 + (lane & 3) * 2;
                        atomicAdd(op + col,     w * (c[mi][ni][hr * 2 + 0] + bias0[ni]));
                        atomicAdd(op + col + 1, w * (c[mi][ni][hr * 2 + 1] + bias1[ni]));
                    }
                }
            }
        }
    }
}

// ---------------------------------------------------------------------------
extern "C" void kernel_launch(void* const* d_in, const int* in_sizes, int n_in,
                              void* d_out, int out_size) {
    const float* x  = (const float*)d_in[0];
    const float* Wg = (const float*)d_in[1];
    const float* W1 = (const float*)d_in[2];
    const float* b1 = (const float*)d_in[3];
    const float* W2 = (const float*)d_in[4];
    const float* b2 = (const float*)d_in[5];
    float* out = (float*)d_out;

    // dynamic smem: 2 stages x (A + B) halves -> bytes
    const int smem1 = 2 * (BM * ASTR + BK * (256 + 8)) * 2;   // 104448
    const int smem2 = 2 * (BM * ASTR + BK * (128 + 8)) * 2;   // 71680
    cudaFuncSetAttribute((const void*)moe_gemm<DM, DF, 256, true, 1>,
                         cudaFuncAttributeMaxDynamicSharedMemorySize, smem1);
    cudaFuncSetAttribute((const void*)moe_gemm<DF, DM, 128, false, 2>,
                         cudaFuncAttributeMaxDynamicSharedMemorySize, smem2);

    prep_kernel<<<(PREP_ITEMS + 255) / 256, 256>>>(out, x, W1, W2);
    gate_kernel<<<S_TOK / 8, 256>>>(x, Wg);
    moe_gemm<DM, DF, 256, true, 1><<<dim3(DF / 256, NSLOT / BM, NE), 256, smem1>>>(b1, out);
    moe_gemm<DF, DM, 128, false, 2><<<dim3(DM / 128, NSLOT / BM, NE), 256, smem2>>>(b2, out);
}